// round 2
// baseline (speedup 1.0000x reference)
#include <cuda_runtime.h>
#include <math.h>

// GAT forward, B=4 N=2048 F=128 H=8 D=64 C=32.
// Softmax trick: exp(lrelu(f1_i+f2_j))/exp(f1_i) = (f1_i+f2_j>0) ? exp(f2_j)
//   : exp(-0.8 f1_i)*exp(0.2 f2_j); the exp(f1_i) factor cancels in softmax.
// R2: weights computed once per (i,j) from a precomputed adjacency bitmask and
// applied to all 64 d-columns from registers (f32x2), shfl-reduced over the
// 4 j-word owners. Removes redundant weight math + most LDS from hot loop.

#define BB 4
#define NN 2048
#define FF 128
#define DD 64
#define HH 8
#define CC 32
#define HD (HH*DD)

__device__ __align__(16) float  g_Wh[BB*HH*NN*DD];   // [b,h,n,d] 16MB
__device__ __align__(16) float2 g_F1R[BB*HH*NN];     // (f1, exp(-0.8 f1))
__device__ __align__(16) float4 g_F2C[BB*HH*NN];     // (f2, exp(f2), exp(0.2 f2), 0)
__device__ __align__(16) float  g_h[BB*NN*HD];       // [b,n,h*64+d] 16MB
__device__ __align__(16) float  g_Wh2[BB*NN*CC];     // [b,n,c]
__device__ __align__(16) float2 g_G1R[BB*NN];
__device__ __align__(16) float4 g_G2C[BB*NN];
__device__ unsigned g_adjb[BB*NN*64];                // adjacency bitmask, 2MB

typedef unsigned long long u64;

__device__ __forceinline__ u64 dup2(float x) {
    u64 r; asm("mov.b64 %0, {%1, %1};" : "=l"(r) : "f"(x)); return r;
}
__device__ __forceinline__ void fma2(u64& d, u64 a, u64 b) {
    asm("fma.rn.f32x2 %0, %1, %2, %0;" : "+l"(d) : "l"(a), "l"(b));
}
__device__ __forceinline__ u64 addx2(u64 a, u64 b) {
    u64 r; asm("add.rn.f32x2 %0, %1, %2;" : "=l"(r) : "l"(a), "l"(b)); return r;
}
__device__ __forceinline__ float2 unp(u64 v) {
    float2 r; asm("mov.b64 {%0, %1}, %2;" : "=f"(r.x), "=f"(r.y) : "l"(v)); return r;
}

// ---------------- K0: adjacency -> bitmask ----------------
__global__ __launch_bounds__(256) void k0_mask(const int* __restrict__ adj) {
    int gw = (blockIdx.x * 256 + threadIdx.x) >> 5;  // 16384 warps
    int lane = threadIdx.x & 31;
    #pragma unroll 8
    for (int k = 0; k < 32; k++) {
        int wi = gw * 32 + k;                         // 524288 words total
        int v = adj[wi * 32 + lane];
        unsigned m = __ballot_sync(0xffffffffu, v > 0);
        if (lane == 0) g_adjb[wi] = m;
    }
}

// ---------------- K1: Wh[b,h,n,d] = x[b,n,:] @ W[h,:,d] ----------------
__global__ __launch_bounds__(256) void k1_gemm_wh(const float* __restrict__ x,
                                                  const float* __restrict__ W) {
    __shared__ __align__(16) float Xs[64*33];
    __shared__ __align__(16) float Ws[32*128];
    int t = threadIdx.x;
    int tr = t >> 4, tc = t & 15;
    int gr0 = blockIdx.y * 64;
    int gc0 = blockIdx.x * 128;
    u64 acc[4][4];
    #pragma unroll
    for (int i=0;i<4;i++){ acc[i][0]=0; acc[i][1]=0; acc[i][2]=0; acc[i][3]=0; }

    for (int kt = 0; kt < 4; kt++) {
        int k0 = kt*32;
        for (int idx = t; idx < 2048; idx += 256) {
            int row = idx >> 5, kk = idx & 31;
            Xs[row*33 + kk] = x[(gr0+row)*FF + k0 + kk];
        }
        for (int idx = t; idx < 4096; idx += 256) {
            int kk = idx >> 7, c = idx & 127;
            int gc = gc0 + c;
            Ws[idx] = W[(gc>>6)*(FF*DD) + (k0+kk)*DD + (gc&63)];
        }
        __syncthreads();
        #pragma unroll
        for (int kk = 0; kk < 32; kk++) {
            u64 ad[4];
            #pragma unroll
            for (int i=0;i<4;i++) ad[i] = dup2(Xs[(tr*4+i)*33 + kk]);
            const ulonglong2* bp = reinterpret_cast<const ulonglong2*>(&Ws[kk*128 + tc*8]);
            ulonglong2 b01 = bp[0], b23 = bp[1];
            #pragma unroll
            for (int i=0;i<4;i++) {
                fma2(acc[i][0], ad[i], b01.x);
                fma2(acc[i][1], ad[i], b01.y);
                fma2(acc[i][2], ad[i], b23.x);
                fma2(acc[i][3], ad[i], b23.y);
            }
        }
        __syncthreads();
    }
    #pragma unroll
    for (int i=0;i<4;i++) {
        int gr = gr0 + tr*4 + i;
        int b = gr >> 11, n = gr & 2047;
        #pragma unroll
        for (int j=0;j<4;j++) {
            float2 v = unp(acc[i][j]);
            int gc = gc0 + tc*8 + j*2;
            int h = gc >> 6, d = gc & 63;
            float* o = &g_Wh[(((b<<3)|h)*NN + n)*DD + d];
            o[0] = v.x; o[1] = v.y;
        }
    }
}

// ---------------- K2: f1,f2 + exp precompute ----------------
__global__ __launch_bounds__(256) void k2_f(const float* __restrict__ a1,
                                            const float* __restrict__ a2) {
    int tid = blockIdx.x*256 + threadIdx.x;      // 0..65535 = (b*8+h)*2048+n
    int h = (tid >> 11) & 7;
    const float4* wr = reinterpret_cast<const float4*>(&g_Wh[tid*DD]);
    const float4* p1 = reinterpret_cast<const float4*>(&a1[h*DD]);
    const float4* p2 = reinterpret_cast<const float4*>(&a2[h*DD]);
    float f1=0.f, f2=0.f;
    #pragma unroll
    for (int i=0;i<16;i++) {
        float4 w = wr[i], v1 = p1[i], v2 = p2[i];
        f1 += w.x*v1.x + w.y*v1.y + w.z*v1.z + w.w*v1.w;
        f2 += w.x*v2.x + w.y*v2.y + w.z*v2.z + w.w*v2.w;
    }
    g_F1R[tid] = make_float2(f1, expf(-0.8f*f1));
    g_F2C[tid] = make_float4(f2, expf(f2), expf(0.2f*f2), 0.f);
}

// ---------------- K3: h = elu(softmax(mask(e)) @ Wh) ----------------
// CTA = 64 i-rows, one (b,h). Thread (il=t>>2, w=t&3): owns row il, j-word w
// of each 128-j tile. Weight in register -> 32 FFMA2 over all 64 d.
__global__ __launch_bounds__(256) void k3_attn1() {
    __shared__ __align__(16) float Whs[128*64];   // [j][d] 32KB
    __shared__ __align__(16) float4 f2c[128];
    int t = threadIdx.x;
    int il = t >> 2, w = t & 3;
    int i0 = blockIdx.x * 64;
    int h = blockIdx.y, b = blockIdx.z;
    int bh = b*HH + h;
    const float* whbase = g_Wh + (size_t)bh*NN*DD;
    float2 f1r = g_F1R[bh*NN + i0 + il];
    float negf1 = -f1r.x, rmul = f1r.y;
    const unsigned* abrow = g_adjb + (b*NN + i0 + il)*64;
    u64 acc[32];
    #pragma unroll
    for (int i=0;i<32;i++) acc[i] = 0ull;
    float zp = 0.f;

    for (int jt = 0; jt < 16; jt++) {
        __syncthreads();
        const float4* src = reinterpret_cast<const float4*>(whbase + jt*128*DD);
        float4* dst = reinterpret_cast<float4*>(Whs);
        #pragma unroll
        for (int q=0;q<8;q++) dst[t + q*256] = src[t + q*256];
        if (t < 128) f2c[t] = g_F2C[bh*NN + jt*128 + t];
        unsigned bw = abrow[jt*4 + w];
        __syncthreads();
        #pragma unroll 4
        for (int kk = 0; kk < 32; kk++) {
            float4 fc = f2c[w*32 + kk];
            float w1 = (fc.x > negf1) ? fc.y : rmul*fc.z;
            float wv = (bw & (1u<<kk)) ? w1 : 0.f;
            zp += wv;
            u64 wd = dup2(wv);
            const ulonglong2* p = reinterpret_cast<const ulonglong2*>(&Whs[(w*32+kk)*64]);
            #pragma unroll
            for (int q=0;q<16;q++) {
                ulonglong2 v = p[q];
                fma2(acc[2*q],   wd, v.x);
                fma2(acc[2*q+1], wd, v.y);
            }
        }
    }
    // reduce partial sums over the 4 j-word owners (lanes xor 1,2 flip w)
    #pragma unroll
    for (int q=0;q<32;q++) {
        acc[q] = addx2(acc[q], __shfl_xor_sync(0xffffffffu, acc[q], 1));
        acc[q] = addx2(acc[q], __shfl_xor_sync(0xffffffffu, acc[q], 2));
    }
    zp += __shfl_xor_sync(0xffffffffu, zp, 1);
    zp += __shfl_xor_sync(0xffffffffu, zp, 2);
    if (zp < 1e-30f) zp = 1.f;
    float invz = 1.f/zp;

    float4* op = reinterpret_cast<float4*>(
        &g_h[(size_t)(b*NN + i0 + il)*HD + h*DD + w*16]);
    #define K3_EPI(W0) { \
        float o[16]; \
        _Pragma("unroll") \
        for (int q=0;q<8;q++) { \
            float2 v = unp(acc[(W0)*8+q]); \
            float a = v.x*invz, c = v.y*invz; \
            o[2*q]   = a > 0.f ? a : expm1f(a); \
            o[2*q+1] = c > 0.f ? c : expm1f(c); \
        } \
        op[0] = *(float4*)&o[0];  op[1] = *(float4*)&o[4]; \
        op[2] = *(float4*)&o[8];  op[3] = *(float4*)&o[12]; }
    switch (w) {
        case 0: K3_EPI(0); break;
        case 1: K3_EPI(1); break;
        case 2: K3_EPI(2); break;
        default: K3_EPI(3); break;
    }
    #undef K3_EPI
}

// ---------------- K4: Wh2 = h[8192,512] @ Wo[512,32] ----------------
// 32 rows/CTA -> grid 256 (full wave coverage).
__global__ __launch_bounds__(256) void k4_gemm_out(const float* __restrict__ Wo) {
    __shared__ __align__(16) float hs[32*132];
    __shared__ __align__(16) float Wos[128*32];
    int t = threadIdx.x;
    int r = t >> 3, cg = t & 7;
    int gr0 = blockIdx.x * 32;
    u64 acc[2] = {0,0};
    for (int kt = 0; kt < 4; kt++) {
        int k0 = kt*128;
        __syncthreads();
        #pragma unroll
        for (int q=0;q<4;q++) {
            int idx = t + q*256;             // 0..1023 float4s
            int row = idx >> 5, kq = idx & 31;
            *reinterpret_cast<float4*>(&hs[row*132 + kq*4]) =
                *reinterpret_cast<const float4*>(&g_h[(gr0+row)*HD + k0 + kq*4]);
            *reinterpret_cast<float4*>(&Wos[idx*4]) =
                *reinterpret_cast<const float4*>(&Wo[k0*32 + idx*4]);
        }
        __syncthreads();
        #pragma unroll 8
        for (int kk = 0; kk < 128; kk++) {
            u64 a = dup2(hs[r*132 + kk]);
            const ulonglong2* bp = reinterpret_cast<const ulonglong2*>(&Wos[kk*32 + cg*4]);
            ulonglong2 bv = bp[0];
            fma2(acc[0], a, bv.x);
            fma2(acc[1], a, bv.y);
        }
    }
    float2 v0 = unp(acc[0]), v1 = unp(acc[1]);
    float4 o = make_float4(v0.x, v0.y, v1.x, v1.y);
    *reinterpret_cast<float4*>(&g_Wh2[(gr0 + r)*CC + cg*4]) = o;
}

// ---------------- K4b: g1,g2 + exp precompute ----------------
__global__ __launch_bounds__(256) void k4b_g(const float* __restrict__ ao1,
                                             const float* __restrict__ ao2) {
    int tid = blockIdx.x*256 + threadIdx.x;  // 0..8191
    const float4* wr = reinterpret_cast<const float4*>(&g_Wh2[tid*CC]);
    const float4* p1 = reinterpret_cast<const float4*>(ao1);
    const float4* p2 = reinterpret_cast<const float4*>(ao2);
    float g1=0.f, g2=0.f;
    #pragma unroll
    for (int i=0;i<8;i++) {
        float4 w = wr[i], v1=p1[i], v2=p2[i];
        g1 += w.x*v1.x + w.y*v1.y + w.z*v1.z + w.w*v1.w;
        g2 += w.x*v2.x + w.y*v2.y + w.z*v2.z + w.w*v2.w;
    }
    g_G1R[tid] = make_float2(g1, expf(-0.8f*g1));
    g_G2C[tid] = make_float4(g2, expf(g2), expf(0.2f*g2), 0.f);
}

// ---------------- K5: out = softmax(mask(e2)) @ Wh2 ----------------
__global__ __launch_bounds__(256) void k5_attn2(float* __restrict__ out) {
    __shared__ __align__(16) float Ws2[128*32];
    __shared__ __align__(16) float4 g2c[128];
    int t = threadIdx.x;
    int il = t >> 2, w = t & 3;
    int i0 = blockIdx.x * 64;
    int b = blockIdx.y;
    float2 g1r = g_G1R[b*NN + i0 + il];
    float negg = -g1r.x, rmul = g1r.y;
    const unsigned* abrow = g_adjb + (b*NN + i0 + il)*64;
    u64 acc[16];
    #pragma unroll
    for (int i=0;i<16;i++) acc[i] = 0ull;
    float zp = 0.f;

    for (int jt = 0; jt < 16; jt++) {
        __syncthreads();
        const float4* src = reinterpret_cast<const float4*>(&g_Wh2[(b*NN + jt*128)*CC]);
        float4* dst = reinterpret_cast<float4*>(Ws2);
        #pragma unroll
        for (int q=0;q<4;q++) dst[t + q*256] = src[t + q*256];
        if (t < 128) g2c[t] = g_G2C[b*NN + jt*128 + t];
        unsigned bw = abrow[jt*4 + w];
        __syncthreads();
        #pragma unroll 4
        for (int kk = 0; kk < 32; kk++) {
            float4 fc = g2c[w*32 + kk];
            float w1 = (fc.x > negg) ? fc.y : rmul*fc.z;
            float wv = (bw & (1u<<kk)) ? w1 : 0.f;
            zp += wv;
            u64 wd = dup2(wv);
            const ulonglong2* p = reinterpret_cast<const ulonglong2*>(&Ws2[(w*32+kk)*32]);
            #pragma unroll
            for (int q=0;q<8;q++) {
                ulonglong2 v = p[q];
                fma2(acc[2*q],   wd, v.x);
                fma2(acc[2*q+1], wd, v.y);
            }
        }
    }
    #pragma unroll
    for (int q=0;q<16;q++) {
        acc[q] = addx2(acc[q], __shfl_xor_sync(0xffffffffu, acc[q], 1));
        acc[q] = addx2(acc[q], __shfl_xor_sync(0xffffffffu, acc[q], 2));
    }
    zp += __shfl_xor_sync(0xffffffffu, zp, 1);
    zp += __shfl_xor_sync(0xffffffffu, zp, 2);
    if (zp < 1e-30f) zp = 1.f;
    float invz = 1.f/zp;

    float4* op = reinterpret_cast<float4*>(&out[(size_t)(b*NN + i0 + il)*CC + w*8]);
    #define K5_EPI(W0) { \
        float o[8]; \
        _Pragma("unroll") \
        for (int q=0;q<4;q++) { \
            float2 v = unp(acc[(W0)*4+q]); \
            o[2*q] = v.x*invz; o[2*q+1] = v.y*invz; \
        } \
        op[0] = *(float4*)&o[0]; op[1] = *(float4*)&o[4]; }
    switch (w) {
        case 0: K5_EPI(0); break;
        case 1: K5_EPI(1); break;
        case 2: K5_EPI(2); break;
        default: K5_EPI(3); break;
    }
    #undef K5_EPI
}

extern "C" void kernel_launch(void* const* d_in, const int* in_sizes, int n_in,
                              void* d_out, int out_size) {
    const float* x   = (const float*)d_in[0];
    const int*   adj = (const int*)  d_in[1];
    const float* W   = (const float*)d_in[2];
    const float* a1  = (const float*)d_in[3];
    const float* a2  = (const float*)d_in[4];
    const float* Wo  = (const float*)d_in[5];
    const float* ao1 = (const float*)d_in[6];
    const float* ao2 = (const float*)d_in[7];
    float* out = (float*)d_out;

    k0_mask<<<2048, 256>>>(adj);                   // adj -> bitmask
    k1_gemm_wh<<<dim3(4,128), 256>>>(x, W);        // Wh
    k2_f<<<256, 256>>>(a1, a2);                    // f1,f2 + exps
    k3_attn1<<<dim3(32, 8, 4), 256>>>();           // layer-1 attention + ELU
    k4_gemm_out<<<256, 256>>>(Wo);                 // Wh2 = h @ Wo
    k4b_g<<<32, 256>>>(ao1, ao2);                  // g1,g2 + exps
    k5_attn2<<<dim3(32, 4), 256>>>(out);           // layer-2 attention -> out
}

// round 3
// speedup vs baseline: 5.8739x; 5.8739x over previous
#include <cuda_runtime.h>
#include <math.h>

// GAT forward, B=4 N=2048 F=128 H=8 D=64 C=32.
// Softmax trick: exp(lrelu(f1_i+f2_j))/exp(f1_i) = (f1_i+f2_j>0) ? exp(f2_j)
//   : exp(-0.8 f1_i)*exp(0.2 f2_j); exp(f1_i) cancels in softmax.
// R3: per-tile weight materialization in smem (each weight computed once),
// then 8ix8d register-tiled f32x2 GEMM on pre-duplicated, bank-skewed Wh tile.

#define BB 4
#define NN 2048
#define FF 128
#define DD 64
#define HH 8
#define CC 32
#define HD (HH*DD)

__device__ __align__(16) float  g_Wh[BB*HH*NN*DD];   // [b,h,n,d] 16MB
__device__ __align__(16) float2 g_F1R[BB*HH*NN];     // (f1, exp(-0.8 f1))
__device__ __align__(16) float4 g_F2C[BB*HH*NN];     // (f2, exp(f2), exp(0.2 f2), 0)
__device__ __align__(16) float  g_h[BB*NN*HD];       // [b,n,h*64+d] 16MB
__device__ __align__(16) float  g_Wh2[BB*NN*CC];     // [b,n,c]
__device__ __align__(16) float2 g_G1R[BB*NN];
__device__ __align__(16) float4 g_G2C[BB*NN];
__device__ unsigned g_adjbT[BB*64*NN];               // bitmask, TRANSPOSED [b][word][row]

typedef unsigned long long u64;

__device__ __forceinline__ void fma2(u64& d, u64 a, u64 b) {
    asm("fma.rn.f32x2 %0, %1, %2, %0;" : "+l"(d) : "l"(a), "l"(b));
}
__device__ __forceinline__ u64 dup2(float x) {
    u64 r; asm("mov.b64 %0, {%1, %1};" : "=l"(r) : "f"(x)); return r;
}
__device__ __forceinline__ float2 unp(u64 v) {
    float2 r; asm("mov.b64 {%0, %1}, %2;" : "=f"(r.x), "=f"(r.y) : "l"(v)); return r;
}

// ---------------- K0: adjacency -> transposed bitmask ----------------
__global__ __launch_bounds__(256) void k0_mask(const int* __restrict__ adj) {
    int gw = (blockIdx.x * 256 + threadIdx.x) >> 5;  // 0..8191 = b*2048+row
    int lane = threadIdx.x & 31;
    int b = gw >> 11, row = gw & 2047;
    const int* ar = adj + (size_t)gw * NN;
    #pragma unroll 4
    for (int w = 0; w < 64; w++) {
        unsigned m = __ballot_sync(0xffffffffu, ar[w*32 + lane] > 0);
        if (lane == 0) g_adjbT[((b<<6) + w)*NN + row] = m;
    }
}

// ---------------- K1: Wh[b,h,n,d] = x[b,n,:] @ W[h,:,d] ----------------
__global__ __launch_bounds__(256) void k1_gemm_wh(const float* __restrict__ x,
                                                  const float* __restrict__ W) {
    __shared__ __align__(16) float Xs[64*33];
    __shared__ __align__(16) float Ws[32*128];
    int t = threadIdx.x;
    int tr = t >> 4, tc = t & 15;
    int gr0 = blockIdx.y * 64;
    int gc0 = blockIdx.x * 128;
    u64 acc[4][4];
    #pragma unroll
    for (int i=0;i<4;i++){ acc[i][0]=0; acc[i][1]=0; acc[i][2]=0; acc[i][3]=0; }

    for (int kt = 0; kt < 4; kt++) {
        int k0 = kt*32;
        for (int idx = t; idx < 2048; idx += 256) {
            int row = idx >> 5, kk = idx & 31;
            Xs[row*33 + kk] = x[(gr0+row)*FF + k0 + kk];
        }
        for (int idx = t; idx < 4096; idx += 256) {
            int kk = idx >> 7, c = idx & 127;
            int gc = gc0 + c;
            Ws[idx] = W[(gc>>6)*(FF*DD) + (k0+kk)*DD + (gc&63)];
        }
        __syncthreads();
        #pragma unroll
        for (int kk = 0; kk < 32; kk++) {
            u64 ad[4];
            #pragma unroll
            for (int i=0;i<4;i++) ad[i] = dup2(Xs[(tr*4+i)*33 + kk]);
            const ulonglong2* bp = reinterpret_cast<const ulonglong2*>(&Ws[kk*128 + tc*8]);
            ulonglong2 b01 = bp[0], b23 = bp[1];
            #pragma unroll
            for (int i=0;i<4;i++) {
                fma2(acc[i][0], ad[i], b01.x);
                fma2(acc[i][1], ad[i], b01.y);
                fma2(acc[i][2], ad[i], b23.x);
                fma2(acc[i][3], ad[i], b23.y);
            }
        }
        __syncthreads();
    }
    #pragma unroll
    for (int i=0;i<4;i++) {
        int gr = gr0 + tr*4 + i;
        int b = gr >> 11, n = gr & 2047;
        #pragma unroll
        for (int j=0;j<4;j++) {
            float2 v = unp(acc[i][j]);
            int gc = gc0 + tc*8 + j*2;
            int h = gc >> 6, d = gc & 63;
            float* o = &g_Wh[(((b<<3)|h)*NN + n)*DD + d];
            o[0] = v.x; o[1] = v.y;
        }
    }
}

// ---------------- K2: f1,f2 + exp precompute ----------------
__global__ __launch_bounds__(256) void k2_f(const float* __restrict__ a1,
                                            const float* __restrict__ a2) {
    int tid = blockIdx.x*256 + threadIdx.x;      // (b*8+h)*2048+n
    int h = (tid >> 11) & 7;
    const float4* wr = reinterpret_cast<const float4*>(&g_Wh[(size_t)tid*DD]);
    const float4* p1 = reinterpret_cast<const float4*>(&a1[h*DD]);
    const float4* p2 = reinterpret_cast<const float4*>(&a2[h*DD]);
    float f1=0.f, f2=0.f;
    #pragma unroll
    for (int i=0;i<16;i++) {
        float4 w = wr[i], v1 = p1[i], v2 = p2[i];
        f1 += w.x*v1.x + w.y*v1.y + w.z*v1.z + w.w*v1.w;
        f2 += w.x*v2.x + w.y*v2.y + w.z*v2.z + w.w*v2.w;
    }
    g_F1R[tid] = make_float2(f1, expf(-0.8f*f1));
    g_F2C[tid] = make_float4(f2, expf(f2), expf(0.2f*f2), 0.f);
}

// ---------------- K3: h = elu(softmax(mask(e)) @ Wh) ----------------
// CTA: 128 i-rows, one (b,h), 128 threads. Per 32-j tile: weight phase (1 row
// per thread, weights -> ws[32][128], zp in reg), then GEMM micro 8i x 8d
// with weights as natural f32x2 pairs and Wh pre-duplicated (no dup movs).
#define TI3 128
#define TJ3 32
__global__ __launch_bounds__(128) void k3_attn1() {
    __shared__ __align__(16) float Whs[TJ3][160];  // dup'd, chunk dg at dg*20 (bank-clean)
    __shared__ __align__(16) float ws[TJ3][TI3];
    __shared__ __align__(16) float4 f2cs[TJ3];
    __shared__ float zps[TI3];
    int t = threadIdx.x;
    int i0 = blockIdx.x * TI3;
    int h = blockIdx.y, b = blockIdx.z;
    int bh = (b<<3) + h;
    const float* __restrict__ whbase = g_Wh + (size_t)bh*NN*DD;
    float2 f1r = g_F1R[bh*NN + i0 + t];
    float negf1 = -f1r.x, rmul = f1r.y;
    float zacc = 0.f;
    int ig = t >> 3, dg = t & 7;
    u64 acc[32];
    #pragma unroll
    for (int q=0;q<32;q++) acc[q] = 0ull;

    for (int jt = 0; jt < NN/TJ3; jt++) {
        int j0 = jt * TJ3;
        unsigned bw = g_adjbT[((b<<6) + jt)*NN + i0 + t];
        __syncthreads();
        // load Wh tile (32j x 64d), duplicated + skewed
        #pragma unroll
        for (int q = 0; q < 4; q++) {
            int idx = t + q*128;
            int j = idx >> 4, f = idx & 15;
            float4 v = *reinterpret_cast<const float4*>(whbase + (size_t)(j0+j)*DD + f*4);
            float* p = &Whs[j][(f>>1)*20 + (f&1)*8];
            *reinterpret_cast<float4*>(p)   = make_float4(v.x, v.x, v.y, v.y);
            *reinterpret_cast<float4*>(p+4) = make_float4(v.z, v.z, v.w, v.w);
        }
        if (t < TJ3) f2cs[t] = g_F2C[bh*NN + j0 + t];
        __syncthreads();
        // weight phase: row t, all 32 j of tile
        #pragma unroll
        for (int kk = 0; kk < TJ3; kk++) {
            float4 fc = f2cs[kk];
            float w1 = (fc.x > negf1) ? fc.y : rmul*fc.z;
            float wv = (bw & (1u<<kk)) ? w1 : 0.f;
            zacc += wv;
            ws[kk][t] = wv;
        }
        __syncthreads();
        // GEMM: 8i x 8d per thread
        #pragma unroll 4
        for (int j = 0; j < TJ3; j++) {
            const ulonglong2* wp = reinterpret_cast<const ulonglong2*>(&ws[j][ig*8]);
            ulonglong2 wA = wp[0], wB = wp[1];   // pairs (i0,i1)(i2,i3) / (i4,i5)(i6,i7)
            const float* hr = &Whs[j][dg*20];
            ulonglong2 h0 = *reinterpret_cast<const ulonglong2*>(hr);
            ulonglong2 h1 = *reinterpret_cast<const ulonglong2*>(hr+4);
            ulonglong2 h2 = *reinterpret_cast<const ulonglong2*>(hr+8);
            ulonglong2 h3 = *reinterpret_cast<const ulonglong2*>(hr+12);
            fma2(acc[0],  wA.x, h0.x); fma2(acc[1],  wA.x, h0.y);
            fma2(acc[2],  wA.x, h1.x); fma2(acc[3],  wA.x, h1.y);
            fma2(acc[4],  wA.x, h2.x); fma2(acc[5],  wA.x, h2.y);
            fma2(acc[6],  wA.x, h3.x); fma2(acc[7],  wA.x, h3.y);
            fma2(acc[8],  wA.y, h0.x); fma2(acc[9],  wA.y, h0.y);
            fma2(acc[10], wA.y, h1.x); fma2(acc[11], wA.y, h1.y);
            fma2(acc[12], wA.y, h2.x); fma2(acc[13], wA.y, h2.y);
            fma2(acc[14], wA.y, h3.x); fma2(acc[15], wA.y, h3.y);
            fma2(acc[16], wB.x, h0.x); fma2(acc[17], wB.x, h0.y);
            fma2(acc[18], wB.x, h1.x); fma2(acc[19], wB.x, h1.y);
            fma2(acc[20], wB.x, h2.x); fma2(acc[21], wB.x, h2.y);
            fma2(acc[22], wB.x, h3.x); fma2(acc[23], wB.x, h3.y);
            fma2(acc[24], wB.y, h0.x); fma2(acc[25], wB.y, h0.y);
            fma2(acc[26], wB.y, h1.x); fma2(acc[27], wB.y, h1.y);
            fma2(acc[28], wB.y, h2.x); fma2(acc[29], wB.y, h2.y);
            fma2(acc[30], wB.y, h3.x); fma2(acc[31], wB.y, h3.y);
        }
    }
    zps[t] = zacc;
    __syncthreads();
    // epilogue: pairs ip -> rows (ig*8+2ip, +1); dims dg*8..dg*8+7
    #pragma unroll
    for (int ip = 0; ip < 4; ip++) {
        int iA = i0 + ig*8 + ip*2;
        float zA = zps[ig*8 + ip*2];     if (zA < 1e-30f) zA = 1.f;
        float zB = zps[ig*8 + ip*2 + 1]; if (zB < 1e-30f) zB = 1.f;
        float invzA = 1.f/zA, invzB = 1.f/zB;
        float oA[8], oB[8];
        #pragma unroll
        for (int dd = 0; dd < 8; dd++) {
            float2 v = unp(acc[ip*8 + dd]);
            float a = v.x*invzA, c = v.y*invzB;
            oA[dd] = a > 0.f ? a : expm1f(a);
            oB[dd] = c > 0.f ? c : expm1f(c);
        }
        float* pA = &g_h[(size_t)(b*NN + iA)*HD + h*DD + dg*8];
        float* pB = pA + HD;
        *reinterpret_cast<float4*>(pA)   = *reinterpret_cast<float4*>(&oA[0]);
        *reinterpret_cast<float4*>(pA+4) = *reinterpret_cast<float4*>(&oA[4]);
        *reinterpret_cast<float4*>(pB)   = *reinterpret_cast<float4*>(&oB[0]);
        *reinterpret_cast<float4*>(pB+4) = *reinterpret_cast<float4*>(&oB[4]);
    }
}

// ---------------- K4: Wh2 = h[8192,512] @ Wo[512,32] ----------------
__global__ __launch_bounds__(256) void k4_gemm_out(const float* __restrict__ Wo) {
    __shared__ __align__(16) float hs[32*132];
    __shared__ __align__(16) float Wos[128*32];
    int t = threadIdx.x;
    int r = t >> 3, cg = t & 7;
    int gr0 = blockIdx.x * 32;
    u64 acc[2] = {0,0};
    for (int kt = 0; kt < 4; kt++) {
        int k0 = kt*128;
        __syncthreads();
        #pragma unroll
        for (int q=0;q<4;q++) {
            int idx = t + q*256;
            int row = idx >> 5, kq = idx & 31;
            *reinterpret_cast<float4*>(&hs[row*132 + kq*4]) =
                *reinterpret_cast<const float4*>(&g_h[(size_t)(gr0+row)*HD + k0 + kq*4]);
            *reinterpret_cast<float4*>(&Wos[idx*4]) =
                *reinterpret_cast<const float4*>(&Wo[k0*32 + idx*4]);
        }
        __syncthreads();
        #pragma unroll 8
        for (int kk = 0; kk < 128; kk++) {
            u64 a = dup2(hs[r*132 + kk]);
            const ulonglong2* bp = reinterpret_cast<const ulonglong2*>(&Wos[kk*32 + cg*4]);
            ulonglong2 bv = bp[0];
            fma2(acc[0], a, bv.x);
            fma2(acc[1], a, bv.y);
        }
    }
    float2 v0 = unp(acc[0]), v1 = unp(acc[1]);
    float4 o = make_float4(v0.x, v0.y, v1.x, v1.y);
    *reinterpret_cast<float4*>(&g_Wh2[(gr0 + r)*CC + cg*4]) = o;
}

// ---------------- K4b: g1,g2 + exp precompute ----------------
__global__ __launch_bounds__(256) void k4b_g(const float* __restrict__ ao1,
                                             const float* __restrict__ ao2) {
    int tid = blockIdx.x*256 + threadIdx.x;  // 0..8191
    const float4* wr = reinterpret_cast<const float4*>(&g_Wh2[tid*CC]);
    const float4* p1 = reinterpret_cast<const float4*>(ao1);
    const float4* p2 = reinterpret_cast<const float4*>(ao2);
    float g1=0.f, g2=0.f;
    #pragma unroll
    for (int i=0;i<8;i++) {
        float4 w = wr[i], v1=p1[i], v2=p2[i];
        g1 += w.x*v1.x + w.y*v1.y + w.z*v1.z + w.w*v1.w;
        g2 += w.x*v2.x + w.y*v2.y + w.z*v2.z + w.w*v2.w;
    }
    g_G1R[tid] = make_float2(g1, expf(-0.8f*g1));
    g_G2C[tid] = make_float4(g2, expf(g2), expf(0.2f*g2), 0.f);
}

// ---------------- K5: out = softmax(mask(e2)) @ Wh2 ----------------
// Same scheme, 64 i-rows, C=32, micro 4i x 4c.
#define TI5 64
#define TJ5 32
__global__ __launch_bounds__(128) void k5_attn2(float* __restrict__ out) {
    __shared__ __align__(16) float W2s[TJ5][68];   // dup'd, chunk cg at cg*8+(cg>>2)*4
    __shared__ __align__(16) float ws5[TJ5][TI5];
    __shared__ __align__(16) float4 g2cs[TJ5];
    __shared__ float zpsA[TI5], zpsB[TI5];
    int t = threadIdx.x;
    int i0 = blockIdx.x * TI5;
    int b = blockIdx.y;
    int iw = t & 63, jq = t >> 6;                   // weight role
    float2 g1r = g_G1R[b*NN + i0 + iw];
    float negg = -g1r.x, rmul = g1r.y;
    float zacc = 0.f;
    int ig = t >> 3, cg = t & 7;                    // GEMM role: rows ig*4..+3, c cg*4..+3
    u64 acc[8];
    #pragma unroll
    for (int q=0;q<8;q++) acc[q] = 0ull;

    for (int jt = 0; jt < NN/TJ5; jt++) {
        int j0 = jt * TJ5;
        unsigned bw = g_adjbT[((b<<6) + jt)*NN + i0 + iw];
        __syncthreads();
        #pragma unroll
        for (int q = 0; q < 2; q++) {
            int idx = t + q*128;
            int j = idx >> 3, f = idx & 7;
            float4 v = *reinterpret_cast<const float4*>(&g_Wh2[(size_t)(b*NN + j0 + j)*CC + f*4]);
            float* p = &W2s[j][f*8 + (f>>2)*4];
            *reinterpret_cast<float4*>(p)   = make_float4(v.x, v.x, v.y, v.y);
            *reinterpret_cast<float4*>(p+4) = make_float4(v.z, v.z, v.w, v.w);
        }
        if (t < TJ5) g2cs[t] = g_G2C[b*NN + j0 + t];
        __syncthreads();
        #pragma unroll
        for (int kk = 0; kk < 16; kk++) {
            int j = jq*16 + kk;
            float4 fc = g2cs[j];
            float w1 = (fc.x > negg) ? fc.y : rmul*fc.z;
            float wv = (bw & (1u << j)) ? w1 : 0.f;
            zacc += wv;
            ws5[j][iw] = wv;
        }
        __syncthreads();
        #pragma unroll 4
        for (int j = 0; j < TJ5; j++) {
            ulonglong2 w = *reinterpret_cast<const ulonglong2*>(&ws5[j][ig*4]);
            const float* hr = &W2s[j][cg*8 + (cg>>2)*4];
            ulonglong2 h0 = *reinterpret_cast<const ulonglong2*>(hr);
            ulonglong2 h1 = *reinterpret_cast<const ulonglong2*>(hr+4);
            fma2(acc[0], w.x, h0.x); fma2(acc[1], w.x, h0.y);
            fma2(acc[2], w.x, h1.x); fma2(acc[3], w.x, h1.y);
            fma2(acc[4], w.y, h0.x); fma2(acc[5], w.y, h0.y);
            fma2(acc[6], w.y, h1.x); fma2(acc[7], w.y, h1.y);
        }
    }
    if (jq == 0) zpsA[iw] = zacc; else zpsB[iw] = zacc;
    __syncthreads();
    #pragma unroll
    for (int ip = 0; ip < 2; ip++) {
        int iA = i0 + ig*4 + ip*2;
        int rA = ig*4 + ip*2;
        float zA = zpsA[rA]   + zpsB[rA];   if (zA < 1e-30f) zA = 1.f;
        float zB = zpsA[rA+1] + zpsB[rA+1]; if (zB < 1e-30f) zB = 1.f;
        float invzA = 1.f/zA, invzB = 1.f/zB;
        float oA[4], oB[4];
        #pragma unroll
        for (int ccd = 0; ccd < 4; ccd++) {
            float2 v = unp(acc[ip*4 + ccd]);
            oA[ccd] = v.x*invzA;
            oB[ccd] = v.y*invzB;
        }
        float* pA = &out[(size_t)(b*NN + iA)*CC + cg*4];
        *reinterpret_cast<float4*>(pA)      = *reinterpret_cast<float4*>(&oA[0]);
        *reinterpret_cast<float4*>(pA + CC) = *reinterpret_cast<float4*>(&oB[0]);
    }
}

extern "C" void kernel_launch(void* const* d_in, const int* in_sizes, int n_in,
                              void* d_out, int out_size) {
    const float* x   = (const float*)d_in[0];
    const int*   adj = (const int*)  d_in[1];
    const float* W   = (const float*)d_in[2];
    const float* a1  = (const float*)d_in[3];
    const float* a2  = (const float*)d_in[4];
    const float* Wo  = (const float*)d_in[5];
    const float* ao1 = (const float*)d_in[6];
    const float* ao2 = (const float*)d_in[7];
    float* out = (float*)d_out;

    k0_mask<<<1024, 256>>>(adj);                   // adj -> transposed bitmask
    k1_gemm_wh<<<dim3(4,128), 256>>>(x, W);        // Wh
    k2_f<<<256, 256>>>(a1, a2);                    // f1,f2 + exps
    k3_attn1<<<dim3(16, 8, 4), 128>>>();           // layer-1 attention + ELU
    k4_gemm_out<<<256, 256>>>(Wo);                 // Wh2 = h @ Wo
    k4b_g<<<32, 256>>>(ao1, ao2);                  // g1,g2 + exps
    k5_attn2<<<dim3(32, 4), 128>>>(out);           // layer-2 attention -> out
}

// round 5
// speedup vs baseline: 8.6086x; 1.4656x over previous
#include <cuda_runtime.h>
#include <cuda_bf16.h>
#include <math.h>
#include <stdint.h>

// GAT forward, B=4 N=2048 F=128 H=8 D=64 C=32.
// Softmax trick: exp(lrelu(f1_i+f2_j))/exp(f1_i) = (f1_i+f2_j>0) ? exp(f2_j)
//   : exp(-0.8 f1_i)*exp(0.2 f2_j); exp(f1_i) cancels in softmax.
// R5: layer-1 aggregation via mma.sync (HMMA) bf16 split-precision
// (wh*Hh + wh*Hl + wl*Hh). tcgen05 is unavailable: harness PTX targets
// sm_103 (no 'a'), which rejects arch-specific instructions.

#define BB 4
#define NN 2048
#define FF 128
#define DD 64
#define HH 8
#define CC 32
#define HD (HH*DD)

__device__ __align__(16) float  g_Wh[BB*HH*NN*DD];   // [b,h,n,d] fp32 16MB
__device__ __align__(16) float2 g_F1R[BB*HH*NN];     // (f1, exp(-0.8 f1))
__device__ __align__(16) float4 g_F2C[BB*HH*NN];     // (f2, exp(f2), exp(0.2 f2), 0)
__device__ __align__(16) float  g_h[BB*NN*HD];       // [b,n,h*64+d] 16MB
__device__ __align__(16) float  g_Wh2[BB*NN*CC];     // [b,n,c]
__device__ __align__(16) float2 g_G1R[BB*NN];
__device__ __align__(16) float4 g_G2C[BB*NN];
__device__ unsigned g_adjbT[BB*64*NN];               // bitmask, TRANSPOSED [b][word][row]
__device__ __align__(16) __nv_bfloat16 g_WhT_hi[BB*HH*DD*NN];  // WhT bf16 hi [bh][d][j]
__device__ __align__(16) __nv_bfloat16 g_WhT_lo[BB*HH*DD*NN];  // WhT bf16 lo

typedef unsigned long long u64;

__device__ __forceinline__ void fma2(u64& d, u64 a, u64 b) {
    asm("fma.rn.f32x2 %0, %1, %2, %0;" : "+l"(d) : "l"(a), "l"(b));
}
__device__ __forceinline__ u64 dup2(float x) {
    u64 r; asm("mov.b64 %0, {%1, %1};" : "=l"(r) : "f"(x)); return r;
}
__device__ __forceinline__ float2 unp(u64 v) {
    float2 r; asm("mov.b64 {%0, %1}, %2;" : "=f"(r.x), "=f"(r.y) : "l"(v)); return r;
}
__device__ __forceinline__ uint32_t smem_u32(const void* p) {
    uint32_t a;
    asm("{ .reg .u64 tmp; cvta.to.shared.u64 tmp, %1; cvt.u32.u64 %0, tmp; }"
        : "=r"(a) : "l"(p));
    return a;
}
__device__ __forceinline__ void ldsm_x4(uint32_t* r, uint32_t addr) {
    asm volatile("ldmatrix.sync.aligned.m8n8.x4.shared.b16 {%0,%1,%2,%3}, [%4];"
        : "=r"(r[0]), "=r"(r[1]), "=r"(r[2]), "=r"(r[3]) : "r"(addr));
}
__device__ __forceinline__ void ldsm_x2(uint32_t* r, uint32_t addr) {
    asm volatile("ldmatrix.sync.aligned.m8n8.x2.shared.b16 {%0,%1}, [%2];"
        : "=r"(r[0]), "=r"(r[1]) : "r"(addr));
}
__device__ __forceinline__ void mma16816(float* c, const uint32_t* a, const uint32_t* b) {
    asm volatile(
        "mma.sync.aligned.m16n8k16.row.col.f32.bf16.bf16.f32 "
        "{%0,%1,%2,%3}, {%4,%5,%6,%7}, {%8,%9}, {%0,%1,%2,%3};"
        : "+f"(c[0]), "+f"(c[1]), "+f"(c[2]), "+f"(c[3])
        : "r"(a[0]), "r"(a[1]), "r"(a[2]), "r"(a[3]), "r"(b[0]), "r"(b[1]));
}

// ---------------- K0: adjacency -> transposed bitmask ----------------
__global__ __launch_bounds__(256) void k0_mask(const int* __restrict__ adj) {
    int gw = (blockIdx.x * 256 + threadIdx.x) >> 5;  // 0..8191 = b*2048+row
    int lane = threadIdx.x & 31;
    int b = gw >> 11, row = gw & 2047;
    const int* ar = adj + (size_t)gw * NN;
    #pragma unroll 4
    for (int w = 0; w < 64; w++) {
        unsigned m = __ballot_sync(0xffffffffu, ar[w*32 + lane] > 0);
        if (lane == 0) g_adjbT[((b<<6) + w)*NN + row] = m;
    }
}

// ---------------- K1: Wh[b,h,n,d] = x[b,n,:] @ W[h,:,d] ----------------
__global__ __launch_bounds__(256) void k1_gemm_wh(const float* __restrict__ x,
                                                  const float* __restrict__ W) {
    __shared__ __align__(16) float Xs[64*33];
    __shared__ __align__(16) float Ws[32*128];
    int t = threadIdx.x;
    int tr = t >> 4, tc = t & 15;
    int gr0 = blockIdx.y * 64;
    int gc0 = blockIdx.x * 128;
    u64 acc[4][4];
    #pragma unroll
    for (int i=0;i<4;i++){ acc[i][0]=0; acc[i][1]=0; acc[i][2]=0; acc[i][3]=0; }

    for (int kt = 0; kt < 4; kt++) {
        int k0 = kt*32;
        for (int idx = t; idx < 2048; idx += 256) {
            int row = idx >> 5, kk = idx & 31;
            Xs[row*33 + kk] = x[(gr0+row)*FF + k0 + kk];
        }
        for (int idx = t; idx < 4096; idx += 256) {
            int kk = idx >> 7, c = idx & 127;
            int gc = gc0 + c;
            Ws[idx] = W[(gc>>6)*(FF*DD) + (k0+kk)*DD + (gc&63)];
        }
        __syncthreads();
        #pragma unroll
        for (int kk = 0; kk < 32; kk++) {
            u64 ad[4];
            #pragma unroll
            for (int i=0;i<4;i++) ad[i] = dup2(Xs[(tr*4+i)*33 + kk]);
            const ulonglong2* bp = reinterpret_cast<const ulonglong2*>(&Ws[kk*128 + tc*8]);
            ulonglong2 b01 = bp[0], b23 = bp[1];
            #pragma unroll
            for (int i=0;i<4;i++) {
                fma2(acc[i][0], ad[i], b01.x);
                fma2(acc[i][1], ad[i], b01.y);
                fma2(acc[i][2], ad[i], b23.x);
                fma2(acc[i][3], ad[i], b23.y);
            }
        }
        __syncthreads();
    }
    #pragma unroll
    for (int i=0;i<4;i++) {
        int gr = gr0 + tr*4 + i;
        int b = gr >> 11, n = gr & 2047;
        #pragma unroll
        for (int j=0;j<4;j++) {
            float2 v = unp(acc[i][j]);
            int gc = gc0 + tc*8 + j*2;
            int h = gc >> 6, d = gc & 63;
            float* o = &g_Wh[(((b<<3)|h)*NN + n)*DD + d];
            o[0] = v.x; o[1] = v.y;
        }
    }
}

// ---------------- K2: f1,f2 + exp precompute ----------------
__global__ __launch_bounds__(256) void k2_f(const float* __restrict__ a1,
                                            const float* __restrict__ a2) {
    int tid = blockIdx.x*256 + threadIdx.x;      // (b*8+h)*2048+n
    int h = (tid >> 11) & 7;
    const float4* wr = reinterpret_cast<const float4*>(&g_Wh[(size_t)tid*DD]);
    const float4* p1 = reinterpret_cast<const float4*>(&a1[h*DD]);
    const float4* p2 = reinterpret_cast<const float4*>(&a2[h*DD]);
    float f1=0.f, f2=0.f;
    #pragma unroll
    for (int i=0;i<16;i++) {
        float4 w = wr[i], v1 = p1[i], v2 = p2[i];
        f1 += w.x*v1.x + w.y*v1.y + w.z*v1.z + w.w*v1.w;
        f2 += w.x*v2.x + w.y*v2.y + w.z*v2.z + w.w*v2.w;
    }
    g_F1R[tid] = make_float2(f1, expf(-0.8f*f1));
    g_F2C[tid] = make_float4(f2, expf(f2), expf(0.2f*f2), 0.f);
}

// ---------------- K2T: Wh fp32 [bh][n][d] -> WhT bf16 hi/lo [bh][d][n] ----------------
__global__ __launch_bounds__(256) void k2t_transpose() {
    __shared__ float ts[64][129];
    int t = threadIdx.x;
    int nblk = blockIdx.x, bh = blockIdx.y;
    const float* src = g_Wh + ((size_t)bh*NN + nblk*128)*DD;
    #pragma unroll
    for (int q = 0; q < 8; q++) {
        int idx = t + q*256;                 // 0..2047 float4s = 128n x 16c4
        int n = idx >> 4, c4 = idx & 15;
        float4 v = *reinterpret_cast<const float4*>(src + n*DD + c4*4);
        ts[c4*4+0][n] = v.x; ts[c4*4+1][n] = v.y;
        ts[c4*4+2][n] = v.z; ts[c4*4+3][n] = v.w;
    }
    __syncthreads();
    #pragma unroll
    for (int q = 0; q < 4; q++) {
        int task = t + q*256;                // 0..1023 = 64d x 16 chunks(8n)
        int d = task >> 4, nc = task & 15;
        uint32_t hiw[4], low[4];
        #pragma unroll
        for (int p = 0; p < 4; p++) {
            float a = ts[d][nc*8 + 2*p], c = ts[d][nc*8 + 2*p + 1];
            __nv_bfloat162 hp = __floats2bfloat162_rn(a, c);
            float2 hf = __bfloat1622float2(hp);
            __nv_bfloat162 lp = __floats2bfloat162_rn(a - hf.x, c - hf.y);
            hiw[p] = *reinterpret_cast<uint32_t*>(&hp);
            low[p] = *reinterpret_cast<uint32_t*>(&lp);
        }
        size_t off = ((size_t)bh*DD + d)*NN + nblk*128 + nc*8;
        *reinterpret_cast<uint4*>(g_WhT_hi + off) = *reinterpret_cast<uint4*>(hiw);
        *reinterpret_cast<uint4*>(g_WhT_lo + off) = *reinterpret_cast<uint4*>(low);
    }
}

// ---------------- K3: h = elu(softmax(mask(e)) @ Wh), HMMA ----------------
// CTA: 128 i-rows, one (b,h), 256 threads (8 warps; warp w owns 16 i-rows).
// Per 64-j tile: weight phase materializes w[128][64] bf16 hi/lo into padded
// smem (each weight once, z in regs); mma phase: m16n8k16, 4 k-steps x 8
// n-tiles x 3 products. A = w (row-major [i][j]), B = WhT ([d][j], k-contig).
// smem: Ah[128][72] @0 (18432B), Al @18432, Bh[64][72] @36864 (9216B),
//       Bl @46080, zp[2][128] @55296. Total 56320B.
#define K3_SMEM 56320
__global__ __launch_bounds__(256) void k3_attn1_mma() {
    extern __shared__ __align__(16) char smem[];
    char* Ahp = smem;
    char* Alp = smem + 18432;
    char* Bhp = smem + 36864;
    char* Blp = smem + 46080;
    float* zp = reinterpret_cast<float*>(smem + 55296);
    uint32_t sb = smem_u32(smem);

    int t = threadIdx.x;
    int warp = t >> 5, lane = t & 31;
    int i0 = blockIdx.x * 128;
    int h = blockIdx.y, b = blockIdx.z;
    int bh = (b<<3) + h;

    int i = t & 127, jh = t >> 7;          // weight-phase role
    float2 f1r = g_F1R[bh*NN + i0 + i];
    float negf1 = -f1r.x, rmul = f1r.y;
    float zacc = 0.f;
    const __nv_bfloat16* bhsrc = g_WhT_hi + (size_t)bh*DD*NN;
    const __nv_bfloat16* blsrc = g_WhT_lo + (size_t)bh*DD*NN;

    float acc[8][4];
    #pragma unroll
    for (int n=0;n<8;n++){ acc[n][0]=0.f; acc[n][1]=0.f; acc[n][2]=0.f; acc[n][3]=0.f; }

    // ldmatrix source addresses (byte offsets within smem), per lane
    int m0 = warp * 16;
    uint32_t aRow = (uint32_t)(m0 + (lane & 15)) * 144u + ((lane & 16) ? 16u : 0u);
    uint32_t bRow = (uint32_t)(lane & 7) * 144u + (uint32_t)(lane & 8) * 2u;

    for (int jt = 0; jt < 32; jt++) {
        if (jt) __syncthreads();           // prior mma reads done before overwrite
        int j0 = jt * 64;
        // ---- weight phase: row i, 32 j (half jh) ----
        unsigned bw = g_adjbT[((b<<6) + jt*2 + jh)*NN + i0 + i];
        const float4* f2p = &g_F2C[bh*NN + j0 + jh*32];
        #pragma unroll
        for (int oct = 0; oct < 4; oct++) {
            float w[8];
            #pragma unroll
            for (int e = 0; e < 8; e++) {
                float4 fc = __ldg(&f2p[oct*8 + e]);
                float w1 = (fc.x > negf1) ? fc.y : rmul*fc.z;
                w[e] = ((bw >> (oct*8 + e)) & 1u) ? w1 : 0.f;
                zacc += w[e];
            }
            uint32_t hiw[4], low[4];
            #pragma unroll
            for (int p = 0; p < 4; p++) {
                __nv_bfloat162 hp = __floats2bfloat162_rn(w[2*p], w[2*p+1]);
                float2 hf = __bfloat1622float2(hp);
                __nv_bfloat162 lp = __floats2bfloat162_rn(w[2*p]-hf.x, w[2*p+1]-hf.y);
                hiw[p] = *reinterpret_cast<uint32_t*>(&hp);
                low[p] = *reinterpret_cast<uint32_t*>(&lp);
            }
            uint32_t off = (uint32_t)i*144u + (uint32_t)(jh*64 + oct*16);
            *reinterpret_cast<uint4*>(Ahp + off) = *reinterpret_cast<uint4*>(hiw);
            *reinterpret_cast<uint4*>(Alp + off) = *reinterpret_cast<uint4*>(low);
        }
        // ---- B tile: WhT[d][j0..j0+63] hi/lo ----
        {
            int d = t >> 2, c = t & 3;     // 64 d x 4 chunks of 16 j
            const uint4* sh = reinterpret_cast<const uint4*>(bhsrc + (size_t)d*NN + j0 + c*16);
            const uint4* sl = reinterpret_cast<const uint4*>(blsrc + (size_t)d*NN + j0 + c*16);
            uint4 vh0 = sh[0], vh1 = sh[1];
            uint4 vl0 = sl[0], vl1 = sl[1];
            uint32_t off = (uint32_t)d*144u + (uint32_t)c*32u;
            *reinterpret_cast<uint4*>(Bhp + off)      = vh0;
            *reinterpret_cast<uint4*>(Bhp + off + 16) = vh1;
            *reinterpret_cast<uint4*>(Blp + off)      = vl0;
            *reinterpret_cast<uint4*>(Blp + off + 16) = vl1;
        }
        __syncthreads();
        // ---- mma phase ----
        #pragma unroll
        for (int k = 0; k < 4; k++) {
            uint32_t kb = (uint32_t)k * 32u;   // k0*2 bytes
            uint32_t ah[4], al[4];
            ldsm_x4(ah, sb + 0     + aRow + kb);
            ldsm_x4(al, sb + 18432 + aRow + kb);
            #pragma unroll
            for (int n = 0; n < 8; n++) {
                uint32_t bfh[2], bfl[2];
                uint32_t boff = (uint32_t)n * (8u*144u) + bRow + kb;
                ldsm_x2(bfh, sb + 36864 + boff);
                ldsm_x2(bfl, sb + 46080 + boff);
                mma16816(acc[n], ah, bfh);
                mma16816(acc[n], ah, bfl);
                mma16816(acc[n], al, bfh);
            }
        }
    }
    zp[jh*128 + i] = zacc;
    __syncthreads();
    // ---- epilogue: softmax normalize + ELU + store ----
    int r0 = m0 + (lane >> 2);
    int r1 = r0 + 8;
    float z0 = zp[r0] + zp[128 + r0];   if (z0 < 1e-30f) z0 = 1.f;
    float z1 = zp[r1] + zp[128 + r1];   if (z1 < 1e-30f) z1 = 1.f;
    float invz0 = 1.f / z0, invz1 = 1.f / z1;
    float* d0 = &g_h[(size_t)(b*NN + i0 + r0)*HD + h*DD + (lane & 3)*2];
    float* d1 = &g_h[(size_t)(b*NN + i0 + r1)*HD + h*DD + (lane & 3)*2];
    #pragma unroll
    for (int n = 0; n < 8; n++) {
        float v0 = acc[n][0] * invz0, v1 = acc[n][1] * invz0;
        float v2 = acc[n][2] * invz1, v3 = acc[n][3] * invz1;
        float2 o0 = make_float2(v0 > 0.f ? v0 : expm1f(v0),
                                 v1 > 0.f ? v1 : expm1f(v1));
        float2 o1 = make_float2(v2 > 0.f ? v2 : expm1f(v2),
                                 v3 > 0.f ? v3 : expm1f(v3));
        *reinterpret_cast<float2*>(d0 + n*8) = o0;
        *reinterpret_cast<float2*>(d1 + n*8) = o1;
    }
}

// ---------------- K4: Wh2 = h[8192,512] @ Wo[512,32] ----------------
__global__ __launch_bounds__(256) void k4_gemm_out(const float* __restrict__ Wo) {
    __shared__ __align__(16) float hs[32*132];
    __shared__ __align__(16) float Wos[128*32];
    int t = threadIdx.x;
    int r = t >> 3, cg = t & 7;
    int gr0 = blockIdx.x * 32;
    u64 acc[2] = {0,0};
    for (int kt = 0; kt < 4; kt++) {
        int k0 = kt*128;
        __syncthreads();
        #pragma unroll
        for (int q=0;q<4;q++) {
            int idx = t + q*256;
            int row = idx >> 5, kq = idx & 31;
            *reinterpret_cast<float4*>(&hs[row*132 + kq*4]) =
                *reinterpret_cast<const float4*>(&g_h[(size_t)(gr0+row)*HD + k0 + kq*4]);
            *reinterpret_cast<float4*>(&Wos[idx*4]) =
                *reinterpret_cast<const float4*>(&Wo[k0*32 + idx*4]);
        }
        __syncthreads();
        #pragma unroll 8
        for (int kk = 0; kk < 128; kk++) {
            u64 a = dup2(hs[r*132 + kk]);
            const ulonglong2* bp = reinterpret_cast<const ulonglong2*>(&Wos[kk*32 + cg*4]);
            ulonglong2 bv = bp[0];
            fma2(acc[0], a, bv.x);
            fma2(acc[1], a, bv.y);
        }
    }
    float2 v0 = unp(acc[0]), v1 = unp(acc[1]);
    float4 o = make_float4(v0.x, v0.y, v1.x, v1.y);
    *reinterpret_cast<float4*>(&g_Wh2[(gr0 + r)*CC + cg*4]) = o;
}

// ---------------- K4b: g1,g2 + exp precompute ----------------
__global__ __launch_bounds__(256) void k4b_g(const float* __restrict__ ao1,
                                             const float* __restrict__ ao2) {
    int tid = blockIdx.x*256 + threadIdx.x;  // 0..8191
    const float4* wr = reinterpret_cast<const float4*>(&g_Wh2[tid*CC]);
    const float4* p1 = reinterpret_cast<const float4*>(ao1);
    const float4* p2 = reinterpret_cast<const float4*>(ao2);
    float g1=0.f, g2=0.f;
    #pragma unroll
    for (int i=0;i<8;i++) {
        float4 w = wr[i], v1=p1[i], v2=p2[i];
        g1 += w.x*v1.x + w.y*v1.y + w.z*v1.z + w.w*v1.w;
        g2 += w.x*v2.x + w.y*v2.y + w.z*v2.z + w.w*v2.w;
    }
    g_G1R[tid] = make_float2(g1, expf(-0.8f*g1));
    g_G2C[tid] = make_float4(g2, expf(g2), expf(0.2f*g2), 0.f);
}

// ---------------- K5: out = softmax(mask(e2)) @ Wh2 ----------------
#define TI5 64
#define TJ5 32
__global__ __launch_bounds__(128) void k5_attn2(float* __restrict__ out) {
    __shared__ __align__(16) float W2s[TJ5][68];
    __shared__ __align__(16) float ws5[TJ5][TI5];
    __shared__ __align__(16) float4 g2cs[TJ5];
    __shared__ float zpsA[TI5], zpsB[TI5];
    int t = threadIdx.x;
    int i0 = blockIdx.x * TI5;
    int b = blockIdx.y;
    int iw = t & 63, jq = t >> 6;
    float2 g1r = g_G1R[b*NN + i0 + iw];
    float negg = -g1r.x, rmul = g1r.y;
    float zacc = 0.f;
    int ig = t >> 3, cg = t & 7;
    u64 acc[8];
    #pragma unroll
    for (int q=0;q<8;q++) acc[q] = 0ull;

    for (int jt = 0; jt < NN/TJ5; jt++) {
        int j0 = jt * TJ5;
        unsigned bw = g_adjbT[((b<<6) + jt)*NN + i0 + iw];
        __syncthreads();
        #pragma unroll
        for (int q = 0; q < 2; q++) {
            int idx = t + q*128;
            int j = idx >> 3, f = idx & 7;
            float4 v = *reinterpret_cast<const float4*>(&g_Wh2[(size_t)(b*NN + j0 + j)*CC + f*4]);
            float* p = &W2s[j][f*8 + (f>>2)*4];
            *reinterpret_cast<float4*>(p)   = make_float4(v.x, v.x, v.y, v.y);
            *reinterpret_cast<float4*>(p+4) = make_float4(v.z, v.z, v.w, v.w);
        }
        if (t < TJ5) g2cs[t] = g_G2C[b*NN + j0 + t];
        __syncthreads();
        #pragma unroll
        for (int kk = 0; kk < 16; kk++) {
            int j = jq*16 + kk;
            float4 fc = g2cs[j];
            float w1 = (fc.x > negg) ? fc.y : rmul*fc.z;
            float wv = (bw & (1u << j)) ? w1 : 0.f;
            zacc += wv;
            ws5[j][iw] = wv;
        }
        __syncthreads();
        #pragma unroll 4
        for (int j = 0; j < TJ5; j++) {
            ulonglong2 w = *reinterpret_cast<const ulonglong2*>(&ws5[j][ig*4]);
            const float* hr = &W2s[j][cg*8 + (cg>>2)*4];
            ulonglong2 h0 = *reinterpret_cast<const ulonglong2*>(hr);
            ulonglong2 h1 = *reinterpret_cast<const ulonglong2*>(hr+4);
            fma2(acc[0], w.x, h0.x); fma2(acc[1], w.x, h0.y);
            fma2(acc[2], w.x, h1.x); fma2(acc[3], w.x, h1.y);
            fma2(acc[4], w.y, h0.x); fma2(acc[5], w.y, h0.y);
            fma2(acc[6], w.y, h1.x); fma2(acc[7], w.y, h1.y);
        }
    }
    if (jq == 0) zpsA[iw] = zacc; else zpsB[iw] = zacc;
    __syncthreads();
    #pragma unroll
    for (int ip = 0; ip < 2; ip++) {
        int iA = i0 + ig*4 + ip*2;
        int rA = ig*4 + ip*2;
        float zA = zpsA[rA]   + zpsB[rA];   if (zA < 1e-30f) zA = 1.f;
        float zB = zpsA[rA+1] + zpsB[rA+1]; if (zB < 1e-30f) zB = 1.f;
        float invzA = 1.f/zA, invzB = 1.f/zB;
        float oA[4], oB[4];
        #pragma unroll
        for (int ccd = 0; ccd < 4; ccd++) {
            float2 v = unp(acc[ip*4 + ccd]);
            oA[ccd] = v.x*invzA;
            oB[ccd] = v.y*invzB;
        }
        float* pA = &out[(size_t)(b*NN + iA)*CC + cg*4];
        *reinterpret_cast<float4*>(pA)      = *reinterpret_cast<float4*>(&oA[0]);
        *reinterpret_cast<float4*>(pA + CC) = *reinterpret_cast<float4*>(&oB[0]);
    }
}

extern "C" void kernel_launch(void* const* d_in, const int* in_sizes, int n_in,
                              void* d_out, int out_size) {
    const float* x   = (const float*)d_in[0];
    const int*   adj = (const int*)  d_in[1];
    const float* W   = (const float*)d_in[2];
    const float* a1  = (const float*)d_in[3];
    const float* a2  = (const float*)d_in[4];
    const float* Wo  = (const float*)d_in[5];
    const float* ao1 = (const float*)d_in[6];
    const float* ao2 = (const float*)d_in[7];
    float* out = (float*)d_out;

    cudaFuncSetAttribute(k3_attn1_mma,
                         cudaFuncAttributeMaxDynamicSharedMemorySize, K3_SMEM);

    k0_mask<<<1024, 256>>>(adj);                      // adj -> transposed bitmask
    k1_gemm_wh<<<dim3(4,128), 256>>>(x, W);           // Wh
    k2_f<<<256, 256>>>(a1, a2);                       // f1,f2 + exps
    k2t_transpose<<<dim3(16, 32), 256>>>();           // WhT bf16 hi/lo
    k3_attn1_mma<<<dim3(16, 8, 4), 256, K3_SMEM>>>(); // layer-1 attn (HMMA)
    k4_gemm_out<<<256, 256>>>(Wo);                    // Wh2 = h @ Wo
    k4b_g<<<32, 256>>>(ao1, ao2);                     // g1,g2 + exps
    k5_attn2<<<dim3(32, 4), 128>>>(out);              // layer-2 attention -> out
}

// round 6
// speedup vs baseline: 9.7995x; 1.1383x over previous
#include <cuda_runtime.h>
#include <cuda_bf16.h>
#include <math.h>
#include <stdint.h>

// GAT forward, B=4 N=2048 F=128 H=8 D=64 C=32.
// Softmax trick: exp(lrelu(f1_i+f2_j))/exp(f1_i) = (f1_i+f2_j>0) ? exp(f2_j)
//   : exp(-0.8 f1_i)*exp(0.2 f2_j); exp(f1_i) cancels in softmax.
// R6: both attention layers on mma.sync bf16 split-precision
// (wh*Hh + wh*Hl + wl*Hh). tcgen05 unavailable (harness targets sm_103).

#define BB 4
#define NN 2048
#define FF 128
#define DD 64
#define HH 8
#define CC 32
#define HD (HH*DD)

__device__ __align__(16) float  g_Wh[BB*HH*NN*DD];   // [b,h,n,d] fp32 16MB
__device__ __align__(16) float2 g_F1R[BB*HH*NN];     // (f1, exp(-0.8 f1))
__device__ __align__(16) float4 g_F2C[BB*HH*NN];     // (f2, exp(f2), exp(0.2 f2), 0)
__device__ __align__(16) float  g_h[BB*NN*HD];       // [b,n,h*64+d] 16MB
__device__ __align__(16) float  g_Wh2[BB*NN*CC];     // [b,n,c]
__device__ __align__(16) float2 g_G1R[BB*NN];
__device__ __align__(16) float4 g_G2C[BB*NN];
__device__ unsigned g_adjbT[BB*64*NN];               // bitmask, TRANSPOSED [b][word][row]
__device__ __align__(16) __nv_bfloat16 g_WhT_hi[BB*HH*DD*NN];  // WhT bf16 hi [bh][d][j]
__device__ __align__(16) __nv_bfloat16 g_WhT_lo[BB*HH*DD*NN];  // WhT bf16 lo
__device__ __align__(16) __nv_bfloat16 g_Wh2T_hi[BB*CC*NN];    // Wh2T bf16 hi [b][c][j]
__device__ __align__(16) __nv_bfloat16 g_Wh2T_lo[BB*CC*NN];    // Wh2T bf16 lo

typedef unsigned long long u64;

__device__ __forceinline__ void fma2(u64& d, u64 a, u64 b) {
    asm("fma.rn.f32x2 %0, %1, %2, %0;" : "+l"(d) : "l"(a), "l"(b));
}
__device__ __forceinline__ u64 dup2(float x) {
    u64 r; asm("mov.b64 %0, {%1, %1};" : "=l"(r) : "f"(x)); return r;
}
__device__ __forceinline__ float2 unp(u64 v) {
    float2 r; asm("mov.b64 {%0, %1}, %2;" : "=f"(r.x), "=f"(r.y) : "l"(v)); return r;
}
__device__ __forceinline__ uint32_t smem_u32(const void* p) {
    uint32_t a;
    asm("{ .reg .u64 tmp; cvta.to.shared.u64 tmp, %1; cvt.u32.u64 %0, tmp; }"
        : "=r"(a) : "l"(p));
    return a;
}
__device__ __forceinline__ void ldsm_x4(uint32_t* r, uint32_t addr) {
    asm volatile("ldmatrix.sync.aligned.m8n8.x4.shared.b16 {%0,%1,%2,%3}, [%4];"
        : "=r"(r[0]), "=r"(r[1]), "=r"(r[2]), "=r"(r[3]) : "r"(addr));
}
__device__ __forceinline__ void ldsm_x2(uint32_t* r, uint32_t addr) {
    asm volatile("ldmatrix.sync.aligned.m8n8.x2.shared.b16 {%0,%1}, [%2];"
        : "=r"(r[0]), "=r"(r[1]) : "r"(addr));
}
__device__ __forceinline__ void mma16816(float* c, const uint32_t* a, const uint32_t* b) {
    asm volatile(
        "mma.sync.aligned.m16n8k16.row.col.f32.bf16.bf16.f32 "
        "{%0,%1,%2,%3}, {%4,%5,%6,%7}, {%8,%9}, {%0,%1,%2,%3};"
        : "+f"(c[0]), "+f"(c[1]), "+f"(c[2]), "+f"(c[3])
        : "r"(a[0]), "r"(a[1]), "r"(a[2]), "r"(a[3]), "r"(b[0]), "r"(b[1]));
}

// ---------------- K0: adjacency -> transposed bitmask ----------------
__global__ __launch_bounds__(256) void k0_mask(const int* __restrict__ adj) {
    int gw = (blockIdx.x * 256 + threadIdx.x) >> 5;  // 0..8191 = b*2048+row
    int lane = threadIdx.x & 31;
    int b = gw >> 11, row = gw & 2047;
    const int* ar = adj + (size_t)gw * NN;
    #pragma unroll 4
    for (int w = 0; w < 64; w++) {
        unsigned m = __ballot_sync(0xffffffffu, ar[w*32 + lane] > 0);
        if (lane == 0) g_adjbT[((b<<6) + w)*NN + row] = m;
    }
}

// ---------------- K1: Wh[b,h,n,d] = x[b,n,:] @ W[h,:,d] ----------------
__global__ __launch_bounds__(256) void k1_gemm_wh(const float* __restrict__ x,
                                                  const float* __restrict__ W) {
    __shared__ __align__(16) float Xs[64*33];
    __shared__ __align__(16) float Ws[32*128];
    int t = threadIdx.x;
    int tr = t >> 4, tc = t & 15;
    int gr0 = blockIdx.y * 64;
    int gc0 = blockIdx.x * 128;
    u64 acc[4][4];
    #pragma unroll
    for (int i=0;i<4;i++){ acc[i][0]=0; acc[i][1]=0; acc[i][2]=0; acc[i][3]=0; }

    for (int kt = 0; kt < 4; kt++) {
        int k0 = kt*32;
        for (int idx = t; idx < 2048; idx += 256) {
            int row = idx >> 5, kk = idx & 31;
            Xs[row*33 + kk] = x[(gr0+row)*FF + k0 + kk];
        }
        for (int idx = t; idx < 4096; idx += 256) {
            int kk = idx >> 7, c = idx & 127;
            int gc = gc0 + c;
            Ws[idx] = W[(gc>>6)*(FF*DD) + (k0+kk)*DD + (gc&63)];
        }
        __syncthreads();
        #pragma unroll
        for (int kk = 0; kk < 32; kk++) {
            u64 ad[4];
            #pragma unroll
            for (int i=0;i<4;i++) ad[i] = dup2(Xs[(tr*4+i)*33 + kk]);
            const ulonglong2* bp = reinterpret_cast<const ulonglong2*>(&Ws[kk*128 + tc*8]);
            ulonglong2 b01 = bp[0], b23 = bp[1];
            #pragma unroll
            for (int i=0;i<4;i++) {
                fma2(acc[i][0], ad[i], b01.x);
                fma2(acc[i][1], ad[i], b01.y);
                fma2(acc[i][2], ad[i], b23.x);
                fma2(acc[i][3], ad[i], b23.y);
            }
        }
        __syncthreads();
    }
    #pragma unroll
    for (int i=0;i<4;i++) {
        int gr = gr0 + tr*4 + i;
        int b = gr >> 11, n = gr & 2047;
        #pragma unroll
        for (int j=0;j<4;j++) {
            float2 v = unp(acc[i][j]);
            int gc = gc0 + tc*8 + j*2;
            int h = gc >> 6, d = gc & 63;
            float* o = &g_Wh[(((b<<3)|h)*NN + n)*DD + d];
            o[0] = v.x; o[1] = v.y;
        }
    }
}

// ---------------- K2: f1,f2 + exp precompute ----------------
__global__ __launch_bounds__(256) void k2_f(const float* __restrict__ a1,
                                            const float* __restrict__ a2) {
    int tid = blockIdx.x*256 + threadIdx.x;      // (b*8+h)*2048+n
    int h = (tid >> 11) & 7;
    const float4* wr = reinterpret_cast<const float4*>(&g_Wh[(size_t)tid*DD]);
    const float4* p1 = reinterpret_cast<const float4*>(&a1[h*DD]);
    const float4* p2 = reinterpret_cast<const float4*>(&a2[h*DD]);
    float f1=0.f, f2=0.f;
    #pragma unroll
    for (int i=0;i<16;i++) {
        float4 w = wr[i], v1 = p1[i], v2 = p2[i];
        f1 += w.x*v1.x + w.y*v1.y + w.z*v1.z + w.w*v1.w;
        f2 += w.x*v2.x + w.y*v2.y + w.z*v2.z + w.w*v2.w;
    }
    g_F1R[tid] = make_float2(f1, expf(-0.8f*f1));
    g_F2C[tid] = make_float4(f2, expf(f2), expf(0.2f*f2), 0.f);
}

// ---------------- K2T: Wh fp32 [bh][n][d] -> WhT bf16 hi/lo [bh][d][n] ----------------
__global__ __launch_bounds__(256) void k2t_transpose() {
    __shared__ float ts[64][129];
    int t = threadIdx.x;
    int nblk = blockIdx.x, bh = blockIdx.y;
    const float* src = g_Wh + ((size_t)bh*NN + nblk*128)*DD;
    #pragma unroll
    for (int q = 0; q < 8; q++) {
        int idx = t + q*256;                 // 0..2047 float4s = 128n x 16c4
        int n = idx >> 4, c4 = idx & 15;
        float4 v = *reinterpret_cast<const float4*>(src + n*DD + c4*4);
        ts[c4*4+0][n] = v.x; ts[c4*4+1][n] = v.y;
        ts[c4*4+2][n] = v.z; ts[c4*4+3][n] = v.w;
    }
    __syncthreads();
    #pragma unroll
    for (int q = 0; q < 4; q++) {
        int task = t + q*256;                // 0..1023 = 64d x 16 chunks(8n)
        int d = task >> 4, nc = task & 15;
        uint32_t hiw[4], low[4];
        #pragma unroll
        for (int p = 0; p < 4; p++) {
            float a = ts[d][nc*8 + 2*p], c = ts[d][nc*8 + 2*p + 1];
            __nv_bfloat162 hp = __floats2bfloat162_rn(a, c);
            float2 hf = __bfloat1622float2(hp);
            __nv_bfloat162 lp = __floats2bfloat162_rn(a - hf.x, c - hf.y);
            hiw[p] = *reinterpret_cast<uint32_t*>(&hp);
            low[p] = *reinterpret_cast<uint32_t*>(&lp);
        }
        size_t off = ((size_t)bh*DD + d)*NN + nblk*128 + nc*8;
        *reinterpret_cast<uint4*>(g_WhT_hi + off) = *reinterpret_cast<uint4*>(hiw);
        *reinterpret_cast<uint4*>(g_WhT_lo + off) = *reinterpret_cast<uint4*>(low);
    }
}

// ---------------- K3: h = elu(softmax(mask(e)) @ Wh), HMMA ----------------
// (unchanged from R5 — 128 i-rows/CTA, 64-j tiles, 3-product split bf16)
#define K3_SMEM 56320
__global__ __launch_bounds__(256) void k3_attn1_mma() {
    extern __shared__ __align__(16) char smem[];
    char* Ahp = smem;
    char* Alp = smem + 18432;
    char* Bhp = smem + 36864;
    char* Blp = smem + 46080;
    float* zp = reinterpret_cast<float*>(smem + 55296);
    uint32_t sb = smem_u32(smem);

    int t = threadIdx.x;
    int warp = t >> 5, lane = t & 31;
    int i0 = blockIdx.x * 128;
    int h = blockIdx.y, b = blockIdx.z;
    int bh = (b<<3) + h;

    int i = t & 127, jh = t >> 7;
    float2 f1r = g_F1R[bh*NN + i0 + i];
    float negf1 = -f1r.x, rmul = f1r.y;
    float zacc = 0.f;
    const __nv_bfloat16* bhsrc = g_WhT_hi + (size_t)bh*DD*NN;
    const __nv_bfloat16* blsrc = g_WhT_lo + (size_t)bh*DD*NN;

    float acc[8][4];
    #pragma unroll
    for (int n=0;n<8;n++){ acc[n][0]=0.f; acc[n][1]=0.f; acc[n][2]=0.f; acc[n][3]=0.f; }

    int m0 = warp * 16;
    uint32_t aRow = (uint32_t)(m0 + (lane & 15)) * 144u + ((lane & 16) ? 16u : 0u);
    uint32_t bRow = (uint32_t)(lane & 7) * 144u + (uint32_t)(lane & 8) * 2u;

    for (int jt = 0; jt < 32; jt++) {
        if (jt) __syncthreads();
        int j0 = jt * 64;
        unsigned bw = g_adjbT[((b<<6) + jt*2 + jh)*NN + i0 + i];
        const float4* f2p = &g_F2C[bh*NN + j0 + jh*32];
        #pragma unroll
        for (int oct = 0; oct < 4; oct++) {
            float w[8];
            #pragma unroll
            for (int e = 0; e < 8; e++) {
                float4 fc = __ldg(&f2p[oct*8 + e]);
                float w1 = (fc.x > negf1) ? fc.y : rmul*fc.z;
                w[e] = ((bw >> (oct*8 + e)) & 1u) ? w1 : 0.f;
                zacc += w[e];
            }
            uint32_t hiw[4], low[4];
            #pragma unroll
            for (int p = 0; p < 4; p++) {
                __nv_bfloat162 hp = __floats2bfloat162_rn(w[2*p], w[2*p+1]);
                float2 hf = __bfloat1622float2(hp);
                __nv_bfloat162 lp = __floats2bfloat162_rn(w[2*p]-hf.x, w[2*p+1]-hf.y);
                hiw[p] = *reinterpret_cast<uint32_t*>(&hp);
                low[p] = *reinterpret_cast<uint32_t*>(&lp);
            }
            uint32_t off = (uint32_t)i*144u + (uint32_t)(jh*64 + oct*16);
            *reinterpret_cast<uint4*>(Ahp + off) = *reinterpret_cast<uint4*>(hiw);
            *reinterpret_cast<uint4*>(Alp + off) = *reinterpret_cast<uint4*>(low);
        }
        {
            int d = t >> 2, c = t & 3;
            const uint4* sh = reinterpret_cast<const uint4*>(bhsrc + (size_t)d*NN + j0 + c*16);
            const uint4* sl = reinterpret_cast<const uint4*>(blsrc + (size_t)d*NN + j0 + c*16);
            uint4 vh0 = sh[0], vh1 = sh[1];
            uint4 vl0 = sl[0], vl1 = sl[1];
            uint32_t off = (uint32_t)d*144u + (uint32_t)c*32u;
            *reinterpret_cast<uint4*>(Bhp + off)      = vh0;
            *reinterpret_cast<uint4*>(Bhp + off + 16) = vh1;
            *reinterpret_cast<uint4*>(Blp + off)      = vl0;
            *reinterpret_cast<uint4*>(Blp + off + 16) = vl1;
        }
        __syncthreads();
        #pragma unroll
        for (int k = 0; k < 4; k++) {
            uint32_t kb = (uint32_t)k * 32u;
            uint32_t ah[4], al[4];
            ldsm_x4(ah, sb + 0     + aRow + kb);
            ldsm_x4(al, sb + 18432 + aRow + kb);
            #pragma unroll
            for (int n = 0; n < 8; n++) {
                uint32_t bfh[2], bfl[2];
                uint32_t boff = (uint32_t)n * (8u*144u) + bRow + kb;
                ldsm_x2(bfh, sb + 36864 + boff);
                ldsm_x2(bfl, sb + 46080 + boff);
                mma16816(acc[n], ah, bfh);
                mma16816(acc[n], ah, bfl);
                mma16816(acc[n], al, bfh);
            }
        }
    }
    zp[jh*128 + i] = zacc;
    __syncthreads();
    int r0 = m0 + (lane >> 2);
    int r1 = r0 + 8;
    float z0 = zp[r0] + zp[128 + r0];   if (z0 < 1e-30f) z0 = 1.f;
    float z1 = zp[r1] + zp[128 + r1];   if (z1 < 1e-30f) z1 = 1.f;
    float invz0 = 1.f / z0, invz1 = 1.f / z1;
    float* d0 = &g_h[(size_t)(b*NN + i0 + r0)*HD + h*DD + (lane & 3)*2];
    float* d1 = &g_h[(size_t)(b*NN + i0 + r1)*HD + h*DD + (lane & 3)*2];
    #pragma unroll
    for (int n = 0; n < 8; n++) {
        float v0 = acc[n][0] * invz0, v1 = acc[n][1] * invz0;
        float v2 = acc[n][2] * invz1, v3 = acc[n][3] * invz1;
        float2 o0 = make_float2(v0 > 0.f ? v0 : expm1f(v0),
                                 v1 > 0.f ? v1 : expm1f(v1));
        float2 o1 = make_float2(v2 > 0.f ? v2 : expm1f(v2),
                                 v3 > 0.f ? v3 : expm1f(v3));
        *reinterpret_cast<float2*>(d0 + n*8) = o0;
        *reinterpret_cast<float2*>(d1 + n*8) = o1;
    }
}

// ---------------- K4: Wh2 = h[8192,512] @ Wo[512,32] ----------------
__global__ __launch_bounds__(256) void k4_gemm_out(const float* __restrict__ Wo) {
    __shared__ __align__(16) float hs[32*132];
    __shared__ __align__(16) float Wos[128*32];
    int t = threadIdx.x;
    int r = t >> 3, cg = t & 7;
    int gr0 = blockIdx.x * 32;
    u64 acc[2] = {0,0};
    for (int kt = 0; kt < 4; kt++) {
        int k0 = kt*128;
        __syncthreads();
        #pragma unroll
        for (int q=0;q<4;q++) {
            int idx = t + q*256;
            int row = idx >> 5, kq = idx & 31;
            *reinterpret_cast<float4*>(&hs[row*132 + kq*4]) =
                *reinterpret_cast<const float4*>(&g_h[(size_t)(gr0+row)*HD + k0 + kq*4]);
            *reinterpret_cast<float4*>(&Wos[idx*4]) =
                *reinterpret_cast<const float4*>(&Wo[k0*32 + idx*4]);
        }
        __syncthreads();
        #pragma unroll 8
        for (int kk = 0; kk < 128; kk++) {
            u64 a = dup2(hs[r*132 + kk]);
            const ulonglong2* bp = reinterpret_cast<const ulonglong2*>(&Wos[kk*32 + cg*4]);
            ulonglong2 bv = bp[0];
            fma2(acc[0], a, bv.x);
            fma2(acc[1], a, bv.y);
        }
    }
    float2 v0 = unp(acc[0]), v1 = unp(acc[1]);
    float4 o = make_float4(v0.x, v0.y, v1.x, v1.y);
    *reinterpret_cast<float4*>(&g_Wh2[(gr0 + r)*CC + cg*4]) = o;
}

// ---------------- K4b: g1,g2 + exp precompute ----------------
__global__ __launch_bounds__(256) void k4b_g(const float* __restrict__ ao1,
                                             const float* __restrict__ ao2) {
    int tid = blockIdx.x*256 + threadIdx.x;  // 0..8191
    const float4* wr = reinterpret_cast<const float4*>(&g_Wh2[tid*CC]);
    const float4* p1 = reinterpret_cast<const float4*>(ao1);
    const float4* p2 = reinterpret_cast<const float4*>(ao2);
    float g1=0.f, g2=0.f;
    #pragma unroll
    for (int i=0;i<8;i++) {
        float4 w = wr[i], v1=p1[i], v2=p2[i];
        g1 += w.x*v1.x + w.y*v1.y + w.z*v1.z + w.w*v1.w;
        g2 += w.x*v2.x + w.y*v2.y + w.z*v2.z + w.w*v2.w;
    }
    g_G1R[tid] = make_float2(g1, expf(-0.8f*g1));
    g_G2C[tid] = make_float4(g2, expf(g2), expf(0.2f*g2), 0.f);
}

// ---------------- K4T: Wh2 fp32 [b][n][c] -> Wh2T bf16 hi/lo [b][c][n] ----------------
__global__ __launch_bounds__(256) void k4t_transpose() {
    __shared__ float ts[32][132];
    int t = threadIdx.x;
    int nblk = blockIdx.x, b = blockIdx.y;
    const float* src = g_Wh2 + ((size_t)(b*NN) + nblk*128)*CC;
    #pragma unroll
    for (int q = 0; q < 4; q++) {
        int idx = t + q*256;                 // 0..1023 float4s = 128n x 8c4
        int n = idx >> 3, c4 = idx & 7;
        float4 v = *reinterpret_cast<const float4*>(src + n*CC + c4*4);
        ts[c4*4+0][n] = v.x; ts[c4*4+1][n] = v.y;
        ts[c4*4+2][n] = v.z; ts[c4*4+3][n] = v.w;
    }
    __syncthreads();
    int c = t >> 3, nc = t & 7;              // 32c x 8 chunks(16n)
    uint32_t hiw[8], low[8];
    #pragma unroll
    for (int p = 0; p < 8; p++) {
        float a = ts[c][nc*16 + 2*p], d = ts[c][nc*16 + 2*p + 1];
        __nv_bfloat162 hp = __floats2bfloat162_rn(a, d);
        float2 hf = __bfloat1622float2(hp);
        __nv_bfloat162 lp = __floats2bfloat162_rn(a - hf.x, d - hf.y);
        hiw[p] = *reinterpret_cast<uint32_t*>(&hp);
        low[p] = *reinterpret_cast<uint32_t*>(&lp);
    }
    size_t off = ((size_t)(b*CC) + c)*NN + nblk*128 + nc*16;
    *reinterpret_cast<uint4*>(g_Wh2T_hi + off)     = *reinterpret_cast<uint4*>(&hiw[0]);
    *reinterpret_cast<uint4*>(g_Wh2T_hi + off + 8) = *reinterpret_cast<uint4*>(&hiw[4]);
    *reinterpret_cast<uint4*>(g_Wh2T_lo + off)     = *reinterpret_cast<uint4*>(&low[0]);
    *reinterpret_cast<uint4*>(g_Wh2T_lo + off + 8) = *reinterpret_cast<uint4*>(&low[4]);
}

// ---------------- K5: out = softmax(mask(e2)) @ Wh2, HMMA ----------------
// CTA: 64 i-rows, one b, 256 threads (8 warps). Warp w: m-tile (w>>1)*16,
// n-half (w&1)*16 (2 n-tiles of 8 c). Per 64-j tile: weight phase 64i x 64j
// (thread = (i = t&63, jq = t>>6) computes 16 weights), then m16n8k16
// 4k x 2n x 3 products. Same fragment conventions as k3.
__global__ __launch_bounds__(256) void k5_attn2_mma(float* __restrict__ out) {
    __shared__ __align__(16) char Ahp[64*144];   // w hi  [64][72 bf16]
    __shared__ __align__(16) char Alp[64*144];   // w lo
    __shared__ __align__(16) char Bhp[32*144];   // Wh2T hi [32][72 bf16]
    __shared__ __align__(16) char Blp[32*144];   // Wh2T lo
    __shared__ float zp[4][64];
    uint32_t sbA_h = smem_u32(Ahp), sbA_l = smem_u32(Alp);
    uint32_t sbB_h = smem_u32(Bhp), sbB_l = smem_u32(Blp);

    int t = threadIdx.x;
    int warp = t >> 5, lane = t & 31;
    int i0 = blockIdx.x * 64;
    int b = blockIdx.y;

    int i = t & 63, jq = t >> 6;             // weight-phase role
    float2 g1r = g_G1R[b*NN + i0 + i];
    float negg = -g1r.x, rmul = g1r.y;
    float zacc = 0.f;
    const __nv_bfloat16* bhsrc = g_Wh2T_hi + (size_t)(b*CC)*NN;
    const __nv_bfloat16* blsrc = g_Wh2T_lo + (size_t)(b*CC)*NN;

    int mt = warp >> 1, nh = warp & 1;
    float acc[2][4];
    acc[0][0]=0.f; acc[0][1]=0.f; acc[0][2]=0.f; acc[0][3]=0.f;
    acc[1][0]=0.f; acc[1][1]=0.f; acc[1][2]=0.f; acc[1][3]=0.f;

    uint32_t aRow = (uint32_t)(mt*16 + (lane & 15)) * 144u + ((lane & 16) ? 16u : 0u);
    uint32_t bRow = (uint32_t)(lane & 7) * 144u + (uint32_t)(lane & 8) * 2u;

    for (int jt = 0; jt < 32; jt++) {
        if (jt) __syncthreads();
        int j0 = jt * 64;
        // ---- weight phase: row i, 16 j (quarter jq) ----
        unsigned bwf = g_adjbT[((b<<6) + jt*2 + (jq>>1))*NN + i0 + i];
        unsigned bw = (bwf >> ((jq & 1)*16)) & 0xFFFFu;
        const float4* g2p = &g_G2C[b*NN + j0 + jq*16];
        float w[16];
        #pragma unroll
        for (int e = 0; e < 16; e++) {
            float4 fc = __ldg(&g2p[e]);
            float w1 = (fc.x > negg) ? fc.y : rmul*fc.z;
            w[e] = ((bw >> e) & 1u) ? w1 : 0.f;
            zacc += w[e];
        }
        uint32_t hiw[8], low[8];
        #pragma unroll
        for (int p = 0; p < 8; p++) {
            __nv_bfloat162 hp = __floats2bfloat162_rn(w[2*p], w[2*p+1]);
            float2 hf = __bfloat1622float2(hp);
            __nv_bfloat162 lp = __floats2bfloat162_rn(w[2*p]-hf.x, w[2*p+1]-hf.y);
            hiw[p] = *reinterpret_cast<uint32_t*>(&hp);
            low[p] = *reinterpret_cast<uint32_t*>(&lp);
        }
        uint32_t off = (uint32_t)i*144u + (uint32_t)jq*32u;
        *reinterpret_cast<uint4*>(Ahp + off)      = *reinterpret_cast<uint4*>(&hiw[0]);
        *reinterpret_cast<uint4*>(Ahp + off + 16) = *reinterpret_cast<uint4*>(&hiw[4]);
        *reinterpret_cast<uint4*>(Alp + off)      = *reinterpret_cast<uint4*>(&low[0]);
        *reinterpret_cast<uint4*>(Alp + off + 16) = *reinterpret_cast<uint4*>(&low[4]);
        // ---- B tile: Wh2T[c][j0..j0+63] hi/lo ----
        {
            int c = t >> 3, ch = t & 7;      // 32 c x 8 chunks of 8 j (16B)
            uint4 vh = *reinterpret_cast<const uint4*>(bhsrc + (size_t)c*NN + j0 + ch*8);
            uint4 vl = *reinterpret_cast<const uint4*>(blsrc + (size_t)c*NN + j0 + ch*8);
            uint32_t boff = (uint32_t)c*144u + (uint32_t)ch*16u;
            *reinterpret_cast<uint4*>(Bhp + boff) = vh;
            *reinterpret_cast<uint4*>(Blp + boff) = vl;
        }
        __syncthreads();
        // ---- mma phase ----
        #pragma unroll
        for (int k = 0; k < 4; k++) {
            uint32_t kb = (uint32_t)k * 32u;
            uint32_t ah[4], al[4];
            ldsm_x4(ah, sbA_h + aRow + kb);
            ldsm_x4(al, sbA_l + aRow + kb);
            #pragma unroll
            for (int n = 0; n < 2; n++) {
                uint32_t bfh[2], bfl[2];
                uint32_t boff = (uint32_t)(nh*2 + n) * (8u*144u) + bRow + kb;
                ldsm_x2(bfh, sbB_h + boff);
                ldsm_x2(bfl, sbB_l + boff);
                mma16816(acc[n], ah, bfh);
                mma16816(acc[n], ah, bfl);
                mma16816(acc[n], al, bfh);
            }
        }
    }
    zp[jq][i] = zacc;
    __syncthreads();
    // ---- epilogue ----
    int r0 = mt*16 + (lane >> 2);
    int r1 = r0 + 8;
    float z0 = zp[0][r0] + zp[1][r0] + zp[2][r0] + zp[3][r0];
    float z1 = zp[0][r1] + zp[1][r1] + zp[2][r1] + zp[3][r1];
    if (z0 < 1e-30f) z0 = 1.f;
    if (z1 < 1e-30f) z1 = 1.f;
    float invz0 = 1.f / z0, invz1 = 1.f / z1;
    #pragma unroll
    for (int n = 0; n < 2; n++) {
        int c0 = nh*16 + n*8 + (lane & 3)*2;
        float2 o0 = make_float2(acc[n][0]*invz0, acc[n][1]*invz0);
        float2 o1 = make_float2(acc[n][2]*invz1, acc[n][3]*invz1);
        *reinterpret_cast<float2*>(&out[(size_t)(b*NN + i0 + r0)*CC + c0]) = o0;
        *reinterpret_cast<float2*>(&out[(size_t)(b*NN + i0 + r1)*CC + c0]) = o1;
    }
}

extern "C" void kernel_launch(void* const* d_in, const int* in_sizes, int n_in,
                              void* d_out, int out_size) {
    const float* x   = (const float*)d_in[0];
    const int*   adj = (const int*)  d_in[1];
    const float* W   = (const float*)d_in[2];
    const float* a1  = (const float*)d_in[3];
    const float* a2  = (const float*)d_in[4];
    const float* Wo  = (const float*)d_in[5];
    const float* ao1 = (const float*)d_in[6];
    const float* ao2 = (const float*)d_in[7];
    float* out = (float*)d_out;

    cudaFuncSetAttribute(k3_attn1_mma,
                         cudaFuncAttributeMaxDynamicSharedMemorySize, K3_SMEM);

    k0_mask<<<1024, 256>>>(adj);                      // adj -> transposed bitmask
    k1_gemm_wh<<<dim3(4,128), 256>>>(x, W);           // Wh
    k2_f<<<256, 256>>>(a1, a2);                       // f1,f2 + exps
    k2t_transpose<<<dim3(16, 32), 256>>>();           // WhT bf16 hi/lo
    k3_attn1_mma<<<dim3(16, 8, 4), 256, K3_SMEM>>>(); // layer-1 attn (HMMA)
    k4_gemm_out<<<256, 256>>>(Wo);                    // Wh2 = h @ Wo
    k4b_g<<<32, 256>>>(ao1, ao2);                     // g1,g2 + exps
    k4t_transpose<<<dim3(16, 4), 256>>>();            // Wh2T bf16 hi/lo
    k5_attn2_mma<<<dim3(32, 4), 256>>>(out);          // layer-2 attn (HMMA)
}